// round 6
// baseline (speedup 1.0000x reference)
#include <cuda_runtime.h>
#include <cstdint>

#define SLEN 2048
#define EDIM 512
#define HDIM 256
#define NTAG 32
#define START_TAG 30
#define STOP_TAG 31
#define NEGV (-10000.0f)

// ---------------- scratch (device globals; no runtime alloc) ----------------
__device__ float g_emb[SLEN * EDIM];
__device__ float g_px[2][SLEN * 4 * HDIM];
__device__ float g_h[2][SLEN * HDIM];
__device__ float g_feats[SLEN * NTAG];

// ---------------- K0: embedding gather ----------------
__global__ void gather_kernel(const int* __restrict__ sent,
                              const float* __restrict__ embed) {
    int s = blockIdx.x;
    int row = sent[s];
    const float4* src = (const float4*)(embed + (size_t)row * EDIM);
    float4* dst = (float4*)(g_emb + s * EDIM);
    dst[threadIdx.x] = src[threadIdx.x];
}

// ---------------- K1: px = emb @ W_ih^T + b ----------------
#define BM 128
#define BN 128
#define BK 16
#define SPAD 132

__global__ __launch_bounds__(256) void px_gemm_kernel(
    const float* __restrict__ w_f, const float* __restrict__ b_f,
    const float* __restrict__ w_b, const float* __restrict__ b_b)
{
    int dir = blockIdx.z;
    const float* W = dir ? w_b : w_f;
    const float* bias = dir ? b_b : b_f;
    float* C = g_px[dir];

    __shared__ float As[BK * SPAD];
    __shared__ float Bs[BK * SPAD];

    int tid = threadIdx.x;
    int m_block = blockIdx.x * BM;
    int n_block = blockIdx.y * BN;

    int lm = tid >> 2;
    int lk4 = (tid & 3) * 4;
    int ty = tid >> 4;
    int tx = tid & 15;
    int m0 = ty * 8, n0 = tx * 8;

    float acc[8][8];
#pragma unroll
    for (int i = 0; i < 8; i++)
#pragma unroll
        for (int j = 0; j < 8; j++) acc[i][j] = 0.f;

    for (int kt = 0; kt < EDIM; kt += BK) {
#pragma unroll
        for (int h = 0; h < 2; h++) {
            int m = lm + h * 64;
            float4 a = *(const float4*)(g_emb + (m_block + m) * EDIM + kt + lk4);
            As[(lk4 + 0) * SPAD + m] = a.x;
            As[(lk4 + 1) * SPAD + m] = a.y;
            As[(lk4 + 2) * SPAD + m] = a.z;
            As[(lk4 + 3) * SPAD + m] = a.w;
            float4 b = *(const float4*)(W + (size_t)(n_block + m) * EDIM + kt + lk4);
            Bs[(lk4 + 0) * SPAD + m] = b.x;
            Bs[(lk4 + 1) * SPAD + m] = b.y;
            Bs[(lk4 + 2) * SPAD + m] = b.z;
            Bs[(lk4 + 3) * SPAD + m] = b.w;
        }
        __syncthreads();
#pragma unroll
        for (int k = 0; k < BK; k++) {
            float ar[8], br[8];
            *(float4*)(ar + 0) = *(const float4*)(&As[k * SPAD + m0 + 0]);
            *(float4*)(ar + 4) = *(const float4*)(&As[k * SPAD + m0 + 4]);
            *(float4*)(br + 0) = *(const float4*)(&Bs[k * SPAD + n0 + 0]);
            *(float4*)(br + 4) = *(const float4*)(&Bs[k * SPAD + n0 + 4]);
#pragma unroll
            for (int i = 0; i < 8; i++)
#pragma unroll
                for (int j = 0; j < 8; j++) acc[i][j] += ar[i] * br[j];
        }
        __syncthreads();
    }
#pragma unroll
    for (int i = 0; i < 8; i++) {
        int row = m_block + m0 + i;
#pragma unroll
        for (int j4 = 0; j4 < 8; j4 += 4) {
            int n = n_block + n0 + j4;
            float4 v;
            v.x = acc[i][j4 + 0] + bias[n + 0];
            v.y = acc[i][j4 + 1] + bias[n + 1];
            v.z = acc[i][j4 + 2] + bias[n + 2];
            v.w = acc[i][j4 + 3] + bias[n + 3];
            *(float4*)(C + row * (4 * HDIM) + n) = v;
        }
    }
}

// ---------------- K2: recurrent LSTM, W in regs, stamp-flag DSMEM sync ------
// 8-CTA cluster per direction, 512 thr/CTA. Thread (q=tid>>7, lr=tid&127)
// holds 64 w_hh floats (row lr, k-quarter q) in registers.
// red layout: red[q*128 + gate*32 + j]; gate warp reduces with LOCAL index j,
// global unit u = crank*32 + j is used only for px/c0/hout/hbuf addressing.
__device__ __forceinline__ float fast_sigmoid(float x) {
    return __fdividef(1.f, 1.f + __expf(-x));
}
__device__ __forceinline__ float fast_tanh(float x) {
    return 1.f - __fdividef(2.f, __expf(2.f * x) + 1.f);
}

__global__ void __cluster_dims__(8, 1, 1) __launch_bounds__(512, 1) lstm_kernel(
    const float* __restrict__ w_hh_f, const float* __restrict__ w_hh_b,
    const float* __restrict__ h0, const float* __restrict__ c0)
{
    __shared__ __align__(16) float hbuf[2 * HDIM];
    __shared__ __align__(16) float red[2][512];
    __shared__ __align__(16) unsigned int flags[2][8];

    int tid = threadIdx.x;
    int dir = blockIdx.x >> 3;
    uint32_t crank;
    asm("mov.u32 %0, %%cluster_ctarank;" : "=r"(crank));
    int base_u = crank * 32;

    const float* Whh = dir ? w_hh_b : w_hh_f;
    const float* px = g_px[dir];
    float* hout = g_h[dir];

    int q = tid >> 7;                    // k-quarter 0..3
    int lr = tid & 127;                  // local row = gate*32 + j
    int gr = ((lr >> 5) << 8) + base_u + (lr & 31);

    uint64_t w2[32];
    const uint64_t* wsrc = (const uint64_t*)(Whh + (size_t)gr * 256 + q * 64);
#pragma unroll
    for (int j = 0; j < 32; j++) w2[j] = wsrc[j];

    if (tid < 256) hbuf[tid] = h0[dir * HDIM + tid];
    if (tid < 16) flags[tid >> 3][tid & 7] = 0;
    int u = base_u + (tid & 31);         // global unit (gate lanes)
    float c_reg = (tid < 32) ? c0[dir * HDIM + u] : 0.f;

    uint32_t hbuf_sa = (uint32_t)__cvta_generic_to_shared(hbuf);
    uint32_t flag_sa = (uint32_t)__cvta_generic_to_shared(flags);
    volatile unsigned int* vfl = (volatile unsigned int*)flags;

    __syncthreads();
    asm volatile("barrier.cluster.arrive.aligned;" ::: "memory");
    asm volatile("barrier.cluster.wait.aligned;" ::: "memory");

    // step-0 px prefetch (gate lanes)
    float pxi = 0.f, pxf = 0.f, pxg = 0.f, pxo = 0.f;
    if (tid < 32) {
        int s0 = dir ? (SLEN - 1) : 0;
        const float* prow = px + s0 * 1024;
        pxi = __ldg(prow + u);
        pxf = __ldg(prow + 256 + u);
        pxg = __ldg(prow + 512 + u);
        pxo = __ldg(prow + 768 + u);
    }

    for (int step = 0; step < SLEN; step++) {
        int p = step & 1;
        int s = dir ? (SLEN - 1 - step) : step;

        // issue next step's px loads before the wait (independent)
        float npxi = 0.f, npxf = 0.f, npxg = 0.f, npxo = 0.f;
        if (tid < 32 && step + 1 < SLEN) {
            int sn = dir ? (SLEN - 2 - step) : (step + 1);
            const float* prow = px + sn * 1024;
            npxi = __ldg(prow + u);
            npxf = __ldg(prow + 256 + u);
            npxg = __ldg(prow + 512 + u);
            npxo = __ldg(prow + 768 + u);
        }

        // wait for this buffer's 8 stamps (step 0: preloaded with h0)
        if (step > 0) {
            unsigned int need = (unsigned int)step;
            const volatile unsigned int* f = vfl + p * 8;
            for (;;) {
                unsigned int m0 = f[0], m1 = f[1], m2 = f[2], m3 = f[3];
                unsigned int m4 = f[4], m5 = f[5], m6 = f[6], m7 = f[7];
                if (m0 >= need && m1 >= need && m2 >= need && m3 >= need &&
                    m4 >= need && m5 >= need && m6 >= need && m7 >= need) break;
            }
            asm volatile("fence.acq_rel.cluster;" ::: "memory");
        }

        // dot: 32 packed FMAs over this thread's k-quarter
        const uint64_t* h2 = (const uint64_t*)(hbuf + p * HDIM) + q * 32;
        uint64_t a0 = 0ull, a1 = 0ull, a2 = 0ull, a3 = 0ull;
#pragma unroll
        for (int j = 0; j < 32; j += 4) {
            uint64_t h0v = h2[j], h1v = h2[j + 1], h2v = h2[j + 2], h3v = h2[j + 3];
            asm("fma.rn.f32x2 %0, %1, %2, %0;" : "+l"(a0) : "l"(w2[j]),     "l"(h0v));
            asm("fma.rn.f32x2 %0, %1, %2, %0;" : "+l"(a1) : "l"(w2[j + 1]), "l"(h1v));
            asm("fma.rn.f32x2 %0, %1, %2, %0;" : "+l"(a2) : "l"(w2[j + 2]), "l"(h2v));
            asm("fma.rn.f32x2 %0, %1, %2, %0;" : "+l"(a3) : "l"(w2[j + 3]), "l"(h3v));
        }
        float l0, h0f, l1, h1f, l2, h2f, l3, h3f;
        asm("mov.b64 {%0,%1}, %2;" : "=f"(l0), "=f"(h0f) : "l"(a0));
        asm("mov.b64 {%0,%1}, %2;" : "=f"(l1), "=f"(h1f) : "l"(a1));
        asm("mov.b64 {%0,%1}, %2;" : "=f"(l2), "=f"(h2f) : "l"(a2));
        asm("mov.b64 {%0,%1}, %2;" : "=f"(l3), "=f"(h3f) : "l"(a3));
        red[p][tid] = ((l0 + h0f) + (l1 + h1f)) + ((l2 + h2f) + (l3 + h3f));
        __syncthreads();

        if (tid < 32) {
            const float* r = red[p];
            // LOCAL lane index (tid) into red — layout q*128 + gate*32 + j
            float di = (r[tid]       + r[128 + tid]) + (r[256 + tid] + r[384 + tid]);
            float df = (r[32 + tid]  + r[160 + tid]) + (r[288 + tid] + r[416 + tid]);
            float dg = (r[64 + tid]  + r[192 + tid]) + (r[320 + tid] + r[448 + tid]);
            float dz = (r[96 + tid]  + r[224 + tid]) + (r[352 + tid] + r[480 + tid]);
            float ig = fast_sigmoid(pxi + di);
            float fg = fast_sigmoid(pxf + df);
            float gg = fast_tanh(pxg + dg);
            float og = fast_sigmoid(pxo + dz);
            c_reg = fg * c_reg + ig * gg;
            float hnew = og * fast_tanh(c_reg);
            hout[s * HDIM + u] = hnew;

            if (step + 1 < SLEN) {
                int wb = p ^ 1;
                uint32_t dst = hbuf_sa + (((wb * HDIM) + u) << 2);
#pragma unroll
                for (int rr = 0; rr < 8; rr++) {
                    uint32_t ra;
                    asm("mapa.shared::cluster.u32 %0, %1, %2;" : "=r"(ra) : "r"(dst), "r"(rr));
                    asm volatile("st.shared::cluster.f32 [%0], %1;"
                                 :: "r"(ra), "f"(hnew) : "memory");
                }
                __syncwarp();
                int lane = tid & 31;
                if (lane < 8) {
                    // cumulative fence: __syncwarp orders the whole warp's
                    // stores before this lane's fence + stamp store.
                    asm volatile("fence.acq_rel.cluster;" ::: "memory");
                    uint32_t fdst = flag_sa + ((wb * 8 + crank) << 2);
                    uint32_t ra;
                    asm("mapa.shared::cluster.u32 %0, %1, %2;" : "=r"(ra) : "r"(fdst), "r"(lane));
                    asm volatile("st.shared::cluster.u32 [%0], %1;"
                                 :: "r"(ra), "r"((unsigned int)(step + 1)) : "memory");
                }
            }
        }
        pxi = npxi; pxf = npxf; pxg = npxg; pxo = npxo;
    }
    asm volatile("barrier.cluster.arrive.aligned;" ::: "memory");
    asm volatile("barrier.cluster.wait.aligned;" ::: "memory");
}

// ---------------- K3: feats ----------------
#define FEATS_SMEM ((512 * 33 + 8 * 512) * 4)
__global__ __launch_bounds__(256) void feats_kernel(const float* __restrict__ w_tag,
                                                    const float* __restrict__ b_tag)
{
    extern __shared__ float fs[];
    float* wt = fs;
    float* hs = fs + 512 * 33;

    int tid = threadIdx.x;
    for (int idx = tid; idx < NTAG * 512; idx += 256) {
        int t = idx >> 9;
        int k = idx & 511;
        wt[k * 33 + t] = w_tag[idx];
    }
    __syncthreads();

    int warp = tid >> 5, lane = tid & 31;
    float bias = b_tag[lane];
    float* hrow = hs + warp * 512;

#pragma unroll
    for (int p = 0; p < 4; p++) {
        int s = blockIdx.x * 32 + p * 8 + warp;
        float4* dsth = (float4*)hrow;
        const float4* hf4 = (const float4*)(g_h[0] + s * HDIM);
        const float4* hb4 = (const float4*)(g_h[1] + s * HDIM);
        dsth[lane] = hf4[lane];
        dsth[32 + lane] = hf4[32 + lane];
        dsth[64 + lane] = hb4[lane];
        dsth[96 + lane] = hb4[32 + lane];
        __syncwarp();
        float a0 = 0.f, a1 = 0.f, a2 = 0.f, a3 = 0.f;
#pragma unroll 8
        for (int k = 0; k < 512; k += 4) {
            float4 h = *(const float4*)(hrow + k);
            a0 += wt[(k + 0) * 33 + lane] * h.x;
            a1 += wt[(k + 1) * 33 + lane] * h.y;
            a2 += wt[(k + 2) * 33 + lane] * h.z;
            a3 += wt[(k + 3) * 33 + lane] * h.w;
        }
        g_feats[s * NTAG + lane] = (a0 + a1) + (a2 + a3) + bias;
        __syncwarp();
    }
}

// ---------------- K4: Viterbi ----------------
__global__ void __launch_bounds__(32) viterbi_kernel(const float* __restrict__ trans,
                                                     float* __restrict__ out,
                                                     int out_size)
{
    extern __shared__ unsigned char bp[];
    int n = threadIdx.x;
    float tr[NTAG];
#pragma unroll
    for (int p = 0; p < NTAG; p++) tr[p] = trans[n * NTAG + p];

    float fv = (n == START_TAG) ? 0.f : NEGV;
    float f0 = g_feats[n];
    float f1 = g_feats[NTAG + n];
    for (int t = 0; t < SLEN; t++) {
        float f2 = (t + 2 < SLEN) ? g_feats[(t + 2) * NTAG + n] : 0.f;
        float v[NTAG];
#pragma unroll
        for (int p = 0; p < NTAG; p++)
            v[p] = __shfl_sync(0xffffffffu, fv, p) + tr[p];
        float bv[16]; int bi[16];
#pragma unroll
        for (int q2 = 0; q2 < 16; q2++) {
            bool take = v[q2 + 16] > v[q2];
            bv[q2] = take ? v[q2 + 16] : v[q2];
            bi[q2] = take ? q2 + 16 : q2;
        }
#pragma unroll
        for (int st = 8; st > 0; st >>= 1) {
#pragma unroll
            for (int q2 = 0; q2 < 16; q2++) {
                if (q2 < st) {
                    bool take = (bv[q2 + st] > bv[q2]) ||
                                (bv[q2 + st] == bv[q2] && bi[q2 + st] < bi[q2]);
                    bv[q2] = take ? bv[q2 + st] : bv[q2];
                    bi[q2] = take ? bi[q2 + st] : bi[q2];
                }
            }
        }
        fv = bv[0] + f0;
        bp[t * NTAG + n] = (unsigned char)bi[0];
        f0 = f1; f1 = f2;
    }
    float term = fv + trans[STOP_TAG * NTAG + n];
    float bvv = term;
    int bii = n;
#pragma unroll
    for (int off = 16; off > 0; off >>= 1) {
        float ov = __shfl_down_sync(0xffffffffu, bvv, off);
        int oi = __shfl_down_sync(0xffffffffu, bii, off);
        if (ov > bvv || (ov == bvv && oi < bii)) { bvv = ov; bii = oi; }
    }
    if (n == 0) {
        if (out_size > 0) out[0] = bvv;
        int tag = bii;
        if (out_size > SLEN) out[SLEN] = (float)tag;
        for (int t = SLEN - 2; t >= 0; t--) {
            tag = bp[(t + 1) * NTAG + tag];
            if (1 + t < out_size) out[1 + t] = (float)tag;
        }
    }
}

// ---------------- launch -----------------------------------------------------
extern "C" void kernel_launch(void* const* d_in, const int* in_sizes, int n_in,
                              void* d_out, int out_size)
{
    const int*   sent   = (const int*)d_in[0];
    const float* embed  = (const float*)d_in[1];
    const float* w_ih_f = (const float*)d_in[2];
    const float* w_hh_f = (const float*)d_in[3];
    const float* b_f    = (const float*)d_in[4];
    const float* w_ih_b = (const float*)d_in[5];
    const float* w_hh_b = (const float*)d_in[6];
    const float* b_b    = (const float*)d_in[7];
    const float* w_tag  = (const float*)d_in[8];
    const float* b_tag  = (const float*)d_in[9];
    const float* trans  = (const float*)d_in[10];
    const float* h0     = (const float*)d_in[11];
    const float* c0     = (const float*)d_in[12];
    float* out = (float*)d_out;

    cudaFuncSetAttribute(feats_kernel,
                         cudaFuncAttributeMaxDynamicSharedMemorySize, FEATS_SMEM);
    cudaFuncSetAttribute(viterbi_kernel,
                         cudaFuncAttributeMaxDynamicSharedMemorySize, SLEN * NTAG);

    gather_kernel<<<SLEN, EDIM / 4>>>(sent, embed);

    dim3 gg(SLEN / BM, (4 * HDIM) / BN, 2);
    px_gemm_kernel<<<gg, 256>>>(w_ih_f, b_f, w_ih_b, b_b);

    lstm_kernel<<<16, 512>>>(w_hh_f, w_hh_b, h0, c0);

    feats_kernel<<<SLEN / 32, 256, FEATS_SMEM>>>(w_tag, b_tag);

    viterbi_kernel<<<1, 32, SLEN * NTAG>>>(trans, out, out_size);
}

// round 7
// speedup vs baseline: 1.1911x; 1.1911x over previous
#include <cuda_runtime.h>
#include <cstdint>

#define SLEN 2048
#define EDIM 512
#define HDIM 256
#define NTAG 32
#define START_TAG 30
#define STOP_TAG 31
#define NEGV (-10000.0f)

// ---------------- scratch (device globals; no runtime alloc) ----------------
__device__ float g_emb[SLEN * EDIM];
__device__ float g_px[2][SLEN * 4 * HDIM];
__device__ float g_h[2][SLEN * HDIM];
__device__ float g_feats[SLEN * NTAG];

// ---------------- K0: embedding gather ----------------
__global__ void gather_kernel(const int* __restrict__ sent,
                              const float* __restrict__ embed) {
    int s = blockIdx.x;
    int row = sent[s];
    const float4* src = (const float4*)(embed + (size_t)row * EDIM);
    float4* dst = (float4*)(g_emb + s * EDIM);
    dst[threadIdx.x] = src[threadIdx.x];
}

// ---------------- K1: px = emb @ W_ih^T + b ----------------
#define BM 128
#define BN 128
#define BK 16
#define SPAD 132

__global__ __launch_bounds__(256) void px_gemm_kernel(
    const float* __restrict__ w_f, const float* __restrict__ b_f,
    const float* __restrict__ w_b, const float* __restrict__ b_b)
{
    int dir = blockIdx.z;
    const float* W = dir ? w_b : w_f;
    const float* bias = dir ? b_b : b_f;
    float* C = g_px[dir];

    __shared__ float As[BK * SPAD];
    __shared__ float Bs[BK * SPAD];

    int tid = threadIdx.x;
    int m_block = blockIdx.x * BM;
    int n_block = blockIdx.y * BN;

    int lm = tid >> 2;
    int lk4 = (tid & 3) * 4;
    int ty = tid >> 4;
    int tx = tid & 15;
    int m0 = ty * 8, n0 = tx * 8;

    float acc[8][8];
#pragma unroll
    for (int i = 0; i < 8; i++)
#pragma unroll
        for (int j = 0; j < 8; j++) acc[i][j] = 0.f;

    for (int kt = 0; kt < EDIM; kt += BK) {
#pragma unroll
        for (int h = 0; h < 2; h++) {
            int m = lm + h * 64;
            float4 a = *(const float4*)(g_emb + (m_block + m) * EDIM + kt + lk4);
            As[(lk4 + 0) * SPAD + m] = a.x;
            As[(lk4 + 1) * SPAD + m] = a.y;
            As[(lk4 + 2) * SPAD + m] = a.z;
            As[(lk4 + 3) * SPAD + m] = a.w;
            float4 b = *(const float4*)(W + (size_t)(n_block + m) * EDIM + kt + lk4);
            Bs[(lk4 + 0) * SPAD + m] = b.x;
            Bs[(lk4 + 1) * SPAD + m] = b.y;
            Bs[(lk4 + 2) * SPAD + m] = b.z;
            Bs[(lk4 + 3) * SPAD + m] = b.w;
        }
        __syncthreads();
#pragma unroll
        for (int k = 0; k < BK; k++) {
            float ar[8], br[8];
            *(float4*)(ar + 0) = *(const float4*)(&As[k * SPAD + m0 + 0]);
            *(float4*)(ar + 4) = *(const float4*)(&As[k * SPAD + m0 + 4]);
            *(float4*)(br + 0) = *(const float4*)(&Bs[k * SPAD + n0 + 0]);
            *(float4*)(br + 4) = *(const float4*)(&Bs[k * SPAD + n0 + 4]);
#pragma unroll
            for (int i = 0; i < 8; i++)
#pragma unroll
                for (int j = 0; j < 8; j++) acc[i][j] += ar[i] * br[j];
        }
        __syncthreads();
    }
#pragma unroll
    for (int i = 0; i < 8; i++) {
        int row = m_block + m0 + i;
#pragma unroll
        for (int j4 = 0; j4 < 8; j4 += 4) {
            int n = n_block + n0 + j4;
            float4 v;
            v.x = acc[i][j4 + 0] + bias[n + 0];
            v.y = acc[i][j4 + 1] + bias[n + 1];
            v.z = acc[i][j4 + 2] + bias[n + 2];
            v.w = acc[i][j4 + 3] + bias[n + 3];
            *(float4*)(C + row * (4 * HDIM) + n) = v;
        }
    }
}

// ---------------- K2: recurrent LSTM, W in regs, chunked stamp-flag sync ----
// 8-CTA cluster per direction, 512 thr/CTA. Thread (q=tid>>7, lr=tid&127)
// holds 64 w_hh floats in registers. h arrives in per-source-CTA chunks of
// 32 floats; a thread consumes only chunks 2q and 2q+1, polling exactly those
// two flags (ld.acquire.cluster, one broadcast LDS per warp per iteration)
// and computing each 16-FMA half as soon as its chunk lands. The per-step
// __syncthreads is the all-flags-observed join that licenses the gate warp's
// buffer overwrite (anti-dependency), as in R6.
__device__ __forceinline__ float fast_sigmoid(float x) {
    return __fdividef(1.f, 1.f + __expf(-x));
}
__device__ __forceinline__ float fast_tanh(float x) {
    return 1.f - __fdividef(2.f, __expf(2.f * x) + 1.f);
}
__device__ __forceinline__ void poll_flag_acq(uint32_t addr, unsigned int need) {
    unsigned int v;
    do {
        asm volatile("ld.acquire.cluster.shared::cta.u32 %0, [%1];"
                     : "=r"(v) : "r"(addr) : "memory");
    } while (v < need);
}

__global__ void __cluster_dims__(8, 1, 1) __launch_bounds__(512, 1) lstm_kernel(
    const float* __restrict__ w_hh_f, const float* __restrict__ w_hh_b,
    const float* __restrict__ h0, const float* __restrict__ c0)
{
    __shared__ __align__(16) float hbuf[2 * HDIM];
    __shared__ __align__(16) float red[2][512];
    __shared__ __align__(16) unsigned int flags[2][8];

    int tid = threadIdx.x;
    int dir = blockIdx.x >> 3;
    uint32_t crank;
    asm("mov.u32 %0, %%cluster_ctarank;" : "=r"(crank));
    int base_u = crank * 32;

    const float* Whh = dir ? w_hh_b : w_hh_f;
    const float* px = g_px[dir];
    float* hout = g_h[dir];

    int q = tid >> 7;                    // k-quarter 0..3 (chunks 2q, 2q+1)
    int lr = tid & 127;                  // local row = gate*32 + j
    int gr = ((lr >> 5) << 8) + base_u + (lr & 31);

    uint64_t w2[32];
    const uint64_t* wsrc = (const uint64_t*)(Whh + (size_t)gr * 256 + q * 64);
#pragma unroll
    for (int j = 0; j < 32; j++) w2[j] = wsrc[j];

    if (tid < 256) hbuf[tid] = h0[dir * HDIM + tid];
    if (tid < 16) flags[tid >> 3][tid & 7] = 0;
    int u = base_u + (tid & 31);         // global unit (gate lanes)
    float c_reg = (tid < 32) ? c0[dir * HDIM + u] : 0.f;

    uint32_t hbuf_sa = (uint32_t)__cvta_generic_to_shared(hbuf);
    uint32_t flag_sa = (uint32_t)__cvta_generic_to_shared(flags);

    // consumer poll addresses (local flags for chunks 2q, 2q+1; both buffers)
    uint32_t fA0 = flag_sa + ((0 * 8 + 2 * q) << 2);
    uint32_t fB0 = fA0 + 4;
    uint32_t fA1 = flag_sa + ((1 * 8 + 2 * q) << 2);
    uint32_t fB1 = fA1 + 4;

    // producer stamp remote addresses (gate warp lanes 0..7 only)
    uint32_t rf0 = 0, rf1 = 0;
    if (tid < 8) {
        uint32_t l0 = flag_sa + ((0 * 8 + crank) << 2);
        uint32_t l1 = flag_sa + ((1 * 8 + crank) << 2);
        asm("mapa.shared::cluster.u32 %0, %1, %2;" : "=r"(rf0) : "r"(l0), "r"(tid));
        asm("mapa.shared::cluster.u32 %0, %1, %2;" : "=r"(rf1) : "r"(l1), "r"(tid));
    }

    __syncthreads();
    asm volatile("barrier.cluster.arrive.aligned;" ::: "memory");
    asm volatile("barrier.cluster.wait.aligned;" ::: "memory");

    // step-0 px prefetch (gate lanes)
    float pxi = 0.f, pxf = 0.f, pxg = 0.f, pxo = 0.f;
    if (tid < 32) {
        int s0 = dir ? (SLEN - 1) : 0;
        const float* prow = px + s0 * 1024;
        pxi = __ldg(prow + u);
        pxf = __ldg(prow + 256 + u);
        pxg = __ldg(prow + 512 + u);
        pxo = __ldg(prow + 768 + u);
    }

    for (int step = 0; step < SLEN; step++) {
        int p = step & 1;
        int s = dir ? (SLEN - 1 - step) : step;

        // issue next step's px loads before the waits (independent)
        float npxi = 0.f, npxf = 0.f, npxg = 0.f, npxo = 0.f;
        if (tid < 32 && step + 1 < SLEN) {
            int sn = dir ? (SLEN - 2 - step) : (step + 1);
            const float* prow = px + sn * 1024;
            npxi = __ldg(prow + u);
            npxf = __ldg(prow + 256 + u);
            npxg = __ldg(prow + 512 + u);
            npxo = __ldg(prow + 768 + u);
        }

        unsigned int need = (unsigned int)step;
        const uint64_t* h2 = (const uint64_t*)(hbuf + p * HDIM) + q * 32;
        uint64_t a0 = 0ull, a1 = 0ull, a2 = 0ull, a3 = 0ull;

        // ---- chunk A (source CTA 2q): k-pairs 0..15 ----
        if (step > 0) poll_flag_acq(p ? fA1 : fA0, need);
#pragma unroll
        for (int j = 0; j < 16; j += 4) {
            uint64_t h0v = h2[j], h1v = h2[j + 1], h2v = h2[j + 2], h3v = h2[j + 3];
            asm("fma.rn.f32x2 %0, %1, %2, %0;" : "+l"(a0) : "l"(w2[j]),     "l"(h0v));
            asm("fma.rn.f32x2 %0, %1, %2, %0;" : "+l"(a1) : "l"(w2[j + 1]), "l"(h1v));
            asm("fma.rn.f32x2 %0, %1, %2, %0;" : "+l"(a2) : "l"(w2[j + 2]), "l"(h2v));
            asm("fma.rn.f32x2 %0, %1, %2, %0;" : "+l"(a3) : "l"(w2[j + 3]), "l"(h3v));
        }
        // ---- chunk B (source CTA 2q+1): k-pairs 16..31 ----
        if (step > 0) poll_flag_acq(p ? fB1 : fB0, need);
#pragma unroll
        for (int j = 16; j < 32; j += 4) {
            uint64_t h0v = h2[j], h1v = h2[j + 1], h2v = h2[j + 2], h3v = h2[j + 3];
            asm("fma.rn.f32x2 %0, %1, %2, %0;" : "+l"(a0) : "l"(w2[j]),     "l"(h0v));
            asm("fma.rn.f32x2 %0, %1, %2, %0;" : "+l"(a1) : "l"(w2[j + 1]), "l"(h1v));
            asm("fma.rn.f32x2 %0, %1, %2, %0;" : "+l"(a2) : "l"(w2[j + 2]), "l"(h2v));
            asm("fma.rn.f32x2 %0, %1, %2, %0;" : "+l"(a3) : "l"(w2[j + 3]), "l"(h3v));
        }

        float l0, h0f, l1, h1f, l2, h2f, l3, h3f;
        asm("mov.b64 {%0,%1}, %2;" : "=f"(l0), "=f"(h0f) : "l"(a0));
        asm("mov.b64 {%0,%1}, %2;" : "=f"(l1), "=f"(h1f) : "l"(a1));
        asm("mov.b64 {%0,%1}, %2;" : "=f"(l2), "=f"(h2f) : "l"(a2));
        asm("mov.b64 {%0,%1}, %2;" : "=f"(l3), "=f"(h3f) : "l"(a3));
        red[p][tid] = ((l0 + h0f) + (l1 + h1f)) + ((l2 + h2f) + (l3 + h3f));
        // all-flags-observed join: collectively, chunk waits covered all 8
        // flags >= step before anyone proceeds past this barrier.
        __syncthreads();

        if (tid < 32) {
            const float* r = red[p];
            float di = (r[tid]       + r[128 + tid]) + (r[256 + tid] + r[384 + tid]);
            float df = (r[32 + tid]  + r[160 + tid]) + (r[288 + tid] + r[416 + tid]);
            float dg = (r[64 + tid]  + r[192 + tid]) + (r[320 + tid] + r[448 + tid]);
            float dz = (r[96 + tid]  + r[224 + tid]) + (r[352 + tid] + r[480 + tid]);
            float ig = fast_sigmoid(pxi + di);
            float fg = fast_sigmoid(pxf + df);
            float gg = fast_tanh(pxg + dg);
            float og = fast_sigmoid(pxo + dz);
            c_reg = fg * c_reg + ig * gg;
            float hnew = og * fast_tanh(c_reg);

            if (step + 1 < SLEN) {
                int wb = p ^ 1;
                uint32_t dst = hbuf_sa + (((wb * HDIM) + u) << 2);
#pragma unroll
                for (int rr = 0; rr < 8; rr++) {
                    uint32_t ra;
                    asm("mapa.shared::cluster.u32 %0, %1, %2;" : "=r"(ra) : "r"(dst), "r"(rr));
                    asm volatile("st.shared::cluster.f32 [%0], %1;"
                                 :: "r"(ra), "f"(hnew) : "memory");
                }
                __syncwarp();   // intra-warp release/acquire: stamp covers all 32 stores
                if (tid < 8) {
                    uint32_t rm = wb ? rf1 : rf0;
                    asm volatile("st.release.cluster.shared::cluster.u32 [%0], %1;"
                                 :: "r"(rm), "r"((unsigned int)(step + 1)) : "memory");
                }
            }
            hout[s * HDIM + u] = hnew;   // off the comm critical path
        }
        pxi = npxi; pxf = npxf; pxg = npxg; pxo = npxo;
    }
    asm volatile("barrier.cluster.arrive.aligned;" ::: "memory");
    asm volatile("barrier.cluster.wait.aligned;" ::: "memory");
}

// ---------------- K3: feats ----------------
#define FEATS_SMEM ((512 * 33 + 8 * 512) * 4)
__global__ __launch_bounds__(256) void feats_kernel(const float* __restrict__ w_tag,
                                                    const float* __restrict__ b_tag)
{
    extern __shared__ float fs[];
    float* wt = fs;
    float* hs = fs + 512 * 33;

    int tid = threadIdx.x;
    for (int idx = tid; idx < NTAG * 512; idx += 256) {
        int t = idx >> 9;
        int k = idx & 511;
        wt[k * 33 + t] = w_tag[idx];
    }
    __syncthreads();

    int warp = tid >> 5, lane = tid & 31;
    float bias = b_tag[lane];
    float* hrow = hs + warp * 512;

#pragma unroll
    for (int p = 0; p < 4; p++) {
        int s = blockIdx.x * 32 + p * 8 + warp;
        float4* dsth = (float4*)hrow;
        const float4* hf4 = (const float4*)(g_h[0] + s * HDIM);
        const float4* hb4 = (const float4*)(g_h[1] + s * HDIM);
        dsth[lane] = hf4[lane];
        dsth[32 + lane] = hf4[32 + lane];
        dsth[64 + lane] = hb4[lane];
        dsth[96 + lane] = hb4[32 + lane];
        __syncwarp();
        float a0 = 0.f, a1 = 0.f, a2 = 0.f, a3 = 0.f;
#pragma unroll 8
        for (int k = 0; k < 512; k += 4) {
            float4 h = *(const float4*)(hrow + k);
            a0 += wt[(k + 0) * 33 + lane] * h.x;
            a1 += wt[(k + 1) * 33 + lane] * h.y;
            a2 += wt[(k + 2) * 33 + lane] * h.z;
            a3 += wt[(k + 3) * 33 + lane] * h.w;
        }
        g_feats[s * NTAG + lane] = (a0 + a1) + (a2 + a3) + bias;
        __syncwarp();
    }
}

// ---------------- K4: Viterbi ----------------
__global__ void __launch_bounds__(32) viterbi_kernel(const float* __restrict__ trans,
                                                     float* __restrict__ out,
                                                     int out_size)
{
    extern __shared__ unsigned char bp[];
    int n = threadIdx.x;
    float tr[NTAG];
#pragma unroll
    for (int p = 0; p < NTAG; p++) tr[p] = trans[n * NTAG + p];

    float fv = (n == START_TAG) ? 0.f : NEGV;
    float f0 = g_feats[n];
    float f1 = g_feats[NTAG + n];
    for (int t = 0; t < SLEN; t++) {
        float f2 = (t + 2 < SLEN) ? g_feats[(t + 2) * NTAG + n] : 0.f;
        float v[NTAG];
#pragma unroll
        for (int p = 0; p < NTAG; p++)
            v[p] = __shfl_sync(0xffffffffu, fv, p) + tr[p];
        float bv[16]; int bi[16];
#pragma unroll
        for (int q2 = 0; q2 < 16; q2++) {
            bool take = v[q2 + 16] > v[q2];
            bv[q2] = take ? v[q2 + 16] : v[q2];
            bi[q2] = take ? q2 + 16 : q2;
        }
#pragma unroll
        for (int st = 8; st > 0; st >>= 1) {
#pragma unroll
            for (int q2 = 0; q2 < 16; q2++) {
                if (q2 < st) {
                    bool take = (bv[q2 + st] > bv[q2]) ||
                                (bv[q2 + st] == bv[q2] && bi[q2 + st] < bi[q2]);
                    bv[q2] = take ? bv[q2 + st] : bv[q2];
                    bi[q2] = take ? bi[q2 + st] : bi[q2];
                }
            }
        }
        fv = bv[0] + f0;
        bp[t * NTAG + n] = (unsigned char)bi[0];
        f0 = f1; f1 = f2;
    }
    float term = fv + trans[STOP_TAG * NTAG + n];
    float bvv = term;
    int bii = n;
#pragma unroll
    for (int off = 16; off > 0; off >>= 1) {
        float ov = __shfl_down_sync(0xffffffffu, bvv, off);
        int oi = __shfl_down_sync(0xffffffffu, bii, off);
        if (ov > bvv || (ov == bvv && oi < bii)) { bvv = ov; bii = oi; }
    }
    if (n == 0) {
        if (out_size > 0) out[0] = bvv;
        int tag = bii;
        if (out_size > SLEN) out[SLEN] = (float)tag;
        for (int t = SLEN - 2; t >= 0; t--) {
            tag = bp[(t + 1) * NTAG + tag];
            if (1 + t < out_size) out[1 + t] = (float)tag;
        }
    }
}

// ---------------- launch -----------------------------------------------------
extern "C" void kernel_launch(void* const* d_in, const int* in_sizes, int n_in,
                              void* d_out, int out_size)
{
    const int*   sent   = (const int*)d_in[0];
    const float* embed  = (const float*)d_in[1];
    const float* w_ih_f = (const float*)d_in[2];
    const float* w_hh_f = (const float*)d_in[3];
    const float* b_f    = (const float*)d_in[4];
    const float* w_ih_b = (const float*)d_in[5];
    const float* w_hh_b = (const float*)d_in[6];
    const float* b_b    = (const float*)d_in[7];
    const float* w_tag  = (const float*)d_in[8];
    const float* b_tag  = (const float*)d_in[9];
    const float* trans  = (const float*)d_in[10];
    const float* h0     = (const float*)d_in[11];
    const float* c0     = (const float*)d_in[12];
    float* out = (float*)d_out;

    cudaFuncSetAttribute(feats_kernel,
                         cudaFuncAttributeMaxDynamicSharedMemorySize, FEATS_SMEM);
    cudaFuncSetAttribute(viterbi_kernel,
                         cudaFuncAttributeMaxDynamicSharedMemorySize, SLEN * NTAG);

    gather_kernel<<<SLEN, EDIM / 4>>>(sent, embed);

    dim3 gg(SLEN / BM, (4 * HDIM) / BN, 2);
    px_gemm_kernel<<<gg, 256>>>(w_ih_f, b_f, w_ih_b, b_b);

    lstm_kernel<<<16, 512>>>(w_hh_f, w_hh_b, h0, c0);

    feats_kernel<<<SLEN / 32, 256, FEATS_SMEM>>>(w_tag, b_tag);

    viterbi_kernel<<<1, 32, SLEN * NTAG>>>(trans, out, out_size);
}

// round 8
// speedup vs baseline: 1.2459x; 1.0460x over previous
#include <cuda_runtime.h>
#include <cstdint>

#define SLEN 2048
#define EDIM 512
#define HDIM 256
#define NTAG 32
#define START_TAG 30
#define STOP_TAG 31
#define NEGV (-10000.0f)

// ---------------- scratch (device globals; no runtime alloc) ----------------
__device__ float g_px[2][SLEN * 4 * HDIM];
__device__ float g_h[2][SLEN * HDIM];
__device__ float g_feats[SLEN * NTAG];

// ---------------- K1: px = embed[sent] @ W_ih^T + b (gather fused) ----------
#define BM 128
#define BN 128
#define BK 16
#define SPAD 132

__global__ __launch_bounds__(256) void px_gemm_kernel(
    const int* __restrict__ sent, const float* __restrict__ embed,
    const float* __restrict__ w_f, const float* __restrict__ b_f,
    const float* __restrict__ w_b, const float* __restrict__ b_b)
{
    int dir = blockIdx.z;
    const float* W = dir ? w_b : w_f;
    const float* bias = dir ? b_b : b_f;
    float* C = g_px[dir];

    __shared__ float As[BK * SPAD];
    __shared__ float Bs[BK * SPAD];
    __shared__ int sidx[BM];

    int tid = threadIdx.x;
    int m_block = blockIdx.x * BM;
    int n_block = blockIdx.y * BN;

    if (tid < BM) sidx[tid] = sent[m_block + tid];

    int lm = tid >> 2;
    int lk4 = (tid & 3) * 4;
    int ty = tid >> 4;
    int tx = tid & 15;
    int m0 = ty * 8, n0 = tx * 8;

    __syncthreads();
    int arow0 = sidx[lm];
    int arow1 = sidx[lm + 64];

    float acc[8][8];
#pragma unroll
    for (int i = 0; i < 8; i++)
#pragma unroll
        for (int j = 0; j < 8; j++) acc[i][j] = 0.f;

    for (int kt = 0; kt < EDIM; kt += BK) {
#pragma unroll
        for (int h = 0; h < 2; h++) {
            int m = lm + h * 64;
            int arow = h ? arow1 : arow0;
            float4 a = *(const float4*)(embed + (size_t)arow * EDIM + kt + lk4);
            As[(lk4 + 0) * SPAD + m] = a.x;
            As[(lk4 + 1) * SPAD + m] = a.y;
            As[(lk4 + 2) * SPAD + m] = a.z;
            As[(lk4 + 3) * SPAD + m] = a.w;
            float4 b = *(const float4*)(W + (size_t)(n_block + m) * EDIM + kt + lk4);
            Bs[(lk4 + 0) * SPAD + m] = b.x;
            Bs[(lk4 + 1) * SPAD + m] = b.y;
            Bs[(lk4 + 2) * SPAD + m] = b.z;
            Bs[(lk4 + 3) * SPAD + m] = b.w;
        }
        __syncthreads();
#pragma unroll
        for (int k = 0; k < BK; k++) {
            float ar[8], br[8];
            *(float4*)(ar + 0) = *(const float4*)(&As[k * SPAD + m0 + 0]);
            *(float4*)(ar + 4) = *(const float4*)(&As[k * SPAD + m0 + 4]);
            *(float4*)(br + 0) = *(const float4*)(&Bs[k * SPAD + n0 + 0]);
            *(float4*)(br + 4) = *(const float4*)(&Bs[k * SPAD + n0 + 4]);
#pragma unroll
            for (int i = 0; i < 8; i++)
#pragma unroll
                for (int j = 0; j < 8; j++) acc[i][j] += ar[i] * br[j];
        }
        __syncthreads();
    }
#pragma unroll
    for (int i = 0; i < 8; i++) {
        int row = m_block + m0 + i;
#pragma unroll
        for (int j4 = 0; j4 < 8; j4 += 4) {
            int n = n_block + n0 + j4;
            float4 v;
            v.x = acc[i][j4 + 0] + bias[n + 0];
            v.y = acc[i][j4 + 1] + bias[n + 1];
            v.z = acc[i][j4 + 2] + bias[n + 2];
            v.w = acc[i][j4 + 3] + bias[n + 3];
            *(float4*)(C + row * (4 * HDIM) + n) = v;
        }
    }
}

// ---------------- K2: recurrent LSTM, W in regs, per-source mbarriers -------
// 8-CTA cluster per direction, 512 thr/CTA. Thread (q=tid>>7, lr=tid&127)
// holds 64 w_hh floats in registers. 16 mbarriers mbars[buf*8+src], arrive
// count 1, no expect_tx. Producer gate warp: DSMEM h stores to each peer,
// __syncwarp, lanes 0..7 remote release-arrive (cumulative over warp stores).
// Consumer thread waits only its two source barriers (chunks 2q, 2q+1),
// FMA-ing each 16-pair chunk as soon as it lands. __syncthreads is the
// all-sources join licensing buffer reuse (proof as in R6/R7, rel_err 0).
__device__ __forceinline__ float fast_sigmoid(float x) {
    return __fdividef(1.f, 1.f + __expf(-x));
}
__device__ __forceinline__ float fast_tanh(float x) {
    return 1.f - __fdividef(2.f, __expf(2.f * x) + 1.f);
}
__device__ __forceinline__ void wait_mbar(uint32_t addr, uint32_t parity) {
    uint32_t done;
    asm volatile(
        "{\n .reg .pred P;\n"
        " mbarrier.try_wait.parity.acquire.cluster.shared::cta.b64 P, [%1], %2;\n"
        " selp.b32 %0, 1, 0, P;\n}"
        : "=r"(done) : "r"(addr), "r"(parity) : "memory");
    while (!done) {
        asm volatile(
            "{\n .reg .pred P;\n"
            " mbarrier.try_wait.parity.acquire.cluster.shared::cta.b64 P, [%1], %2, 0x989680;\n"
            " selp.b32 %0, 1, 0, P;\n}"
            : "=r"(done) : "r"(addr), "r"(parity) : "memory");
    }
}

__global__ void __cluster_dims__(8, 1, 1) __launch_bounds__(512, 1) lstm_kernel(
    const float* __restrict__ w_hh_f, const float* __restrict__ w_hh_b,
    const float* __restrict__ h0, const float* __restrict__ c0)
{
    __shared__ __align__(16) float hbuf[2 * HDIM];
    __shared__ __align__(16) float red[2][512];
    __shared__ __align__(8) unsigned long long mbars[16];  // [buf*8 + src]

    int tid = threadIdx.x;
    int dir = blockIdx.x >> 3;
    uint32_t crank;
    asm("mov.u32 %0, %%cluster_ctarank;" : "=r"(crank));
    int base_u = crank * 32;

    const float* Whh = dir ? w_hh_b : w_hh_f;
    const float* px = g_px[dir];
    float* hout = g_h[dir];

    int q = tid >> 7;                    // k-quarter 0..3 (chunks 2q, 2q+1)
    int lr = tid & 127;                  // local row = gate*32 + j
    int gr = ((lr >> 5) << 8) + base_u + (lr & 31);

    uint64_t w2[32];
    const uint64_t* wsrc = (const uint64_t*)(Whh + (size_t)gr * 256 + q * 64);
#pragma unroll
    for (int j = 0; j < 32; j++) w2[j] = wsrc[j];

    if (tid < 256) hbuf[tid] = h0[dir * HDIM + tid];
    int u = base_u + (tid & 31);         // global unit (gate lanes)
    float c_reg = (tid < 32) ? c0[dir * HDIM + u] : 0.f;

    uint32_t hbuf_sa = (uint32_t)__cvta_generic_to_shared(hbuf);
    uint32_t mbar_sa = (uint32_t)__cvta_generic_to_shared(mbars);

    if (tid == 0) {
#pragma unroll
        for (int s = 0; s < 16; s++)
            asm volatile("mbarrier.init.shared.b64 [%0], 1;"
                         :: "r"(mbar_sa + s * 8) : "memory");
        asm volatile("fence.mbarrier_init.release.cluster;" ::: "memory");
    }

    // consumer wait addresses: mbars[p*8 + 2q], +1  (local)
    uint32_t mwA0 = mbar_sa + ((0 * 8 + 2 * q) << 3);
    uint32_t mwB0 = mwA0 + 8;
    uint32_t mwA1 = mbar_sa + ((1 * 8 + 2 * q) << 3);
    uint32_t mwB1 = mwA1 + 8;

    // producer addresses, hoisted out of the loop (gate warp only)
    uint32_t rdst0[8], rdst1[8];   // remote hbuf slots, both buffers
    uint32_t rmb0 = 0, rmb1 = 0;   // remote mbarriers (lanes 0..7)
    if (tid < 32) {
        uint32_t d0 = hbuf_sa + ((0 * HDIM + u) << 2);
        uint32_t d1 = hbuf_sa + ((1 * HDIM + u) << 2);
#pragma unroll
        for (int rr = 0; rr < 8; rr++) {
            asm("mapa.shared::cluster.u32 %0, %1, %2;" : "=r"(rdst0[rr]) : "r"(d0), "r"(rr));
            asm("mapa.shared::cluster.u32 %0, %1, %2;" : "=r"(rdst1[rr]) : "r"(d1), "r"(rr));
        }
        if (tid < 8) {
            uint32_t m0a = mbar_sa + ((0 * 8 + crank) << 3);
            uint32_t m1a = mbar_sa + ((1 * 8 + crank) << 3);
            asm("mapa.shared::cluster.u32 %0, %1, %2;" : "=r"(rmb0) : "r"(m0a), "r"(tid));
            asm("mapa.shared::cluster.u32 %0, %1, %2;" : "=r"(rmb1) : "r"(m1a), "r"(tid));
        }
    }

    __syncthreads();
    asm volatile("barrier.cluster.arrive.aligned;" ::: "memory");
    asm volatile("barrier.cluster.wait.aligned;" ::: "memory");

    // step-0 px prefetch (gate lanes)
    float pxi = 0.f, pxf = 0.f, pxg = 0.f, pxo = 0.f;
    if (tid < 32) {
        int s0 = dir ? (SLEN - 1) : 0;
        const float* prow = px + s0 * 1024;
        pxi = __ldg(prow + u);
        pxf = __ldg(prow + 256 + u);
        pxg = __ldg(prow + 512 + u);
        pxo = __ldg(prow + 768 + u);
    }

    uint32_t ph0 = 0, ph1 = 0;    // phase per buffer
    for (int step = 0; step < SLEN; step++) {
        int p = step & 1;
        int s = dir ? (SLEN - 1 - step) : step;

        // issue next step's px loads before the waits (independent)
        float npxi = 0.f, npxf = 0.f, npxg = 0.f, npxo = 0.f;
        if (tid < 32 && step + 1 < SLEN) {
            int sn = dir ? (SLEN - 2 - step) : (step + 1);
            const float* prow = px + sn * 1024;
            npxi = __ldg(prow + u);
            npxf = __ldg(prow + 256 + u);
            npxg = __ldg(prow + 512 + u);
            npxo = __ldg(prow + 768 + u);
        }

        const uint4* h4 = (const uint4*)(hbuf + p * HDIM) + q * 16;
        uint64_t a0 = 0ull, a1 = 0ull, a2 = 0ull, a3 = 0ull;

        // ---- chunk A (source CTA 2q): k-pairs 0..15 ----
        if (step > 0) wait_mbar(p ? mwA1 : mwA0, p ? ph1 : ph0);
#pragma unroll
        for (int j = 0; j < 8; j += 2) {
            uint4 v0 = h4[j], v1 = h4[j + 1];
            uint64_t p0, p1, p2, p3;
            asm("mov.b64 %0, {%1,%2};" : "=l"(p0) : "r"(v0.x), "r"(v0.y));
            asm("mov.b64 %0, {%1,%2};" : "=l"(p1) : "r"(v0.z), "r"(v0.w));
            asm("mov.b64 %0, {%1,%2};" : "=l"(p2) : "r"(v1.x), "r"(v1.y));
            asm("mov.b64 %0, {%1,%2};" : "=l"(p3) : "r"(v1.z), "r"(v1.w));
            asm("fma.rn.f32x2 %0, %1, %2, %0;" : "+l"(a0) : "l"(w2[2 * j]),     "l"(p0));
            asm("fma.rn.f32x2 %0, %1, %2, %0;" : "+l"(a1) : "l"(w2[2 * j + 1]), "l"(p1));
            asm("fma.rn.f32x2 %0, %1, %2, %0;" : "+l"(a2) : "l"(w2[2 * j + 2]), "l"(p2));
            asm("fma.rn.f32x2 %0, %1, %2, %0;" : "+l"(a3) : "l"(w2[2 * j + 3]), "l"(p3));
        }
        // ---- chunk B (source CTA 2q+1): k-pairs 16..31 ----
        if (step > 0) wait_mbar(p ? mwB1 : mwB0, p ? ph1 : ph0);
#pragma unroll
        for (int j = 8; j < 16; j += 2) {
            uint4 v0 = h4[j], v1 = h4[j + 1];
            uint64_t p0, p1, p2, p3;
            asm("mov.b64 %0, {%1,%2};" : "=l"(p0) : "r"(v0.x), "r"(v0.y));
            asm("mov.b64 %0, {%1,%2};" : "=l"(p1) : "r"(v0.z), "r"(v0.w));
            asm("mov.b64 %0, {%1,%2};" : "=l"(p2) : "r"(v1.x), "r"(v1.y));
            asm("mov.b64 %0, {%1,%2};" : "=l"(p3) : "r"(v1.z), "r"(v1.w));
            asm("fma.rn.f32x2 %0, %1, %2, %0;" : "+l"(a0) : "l"(w2[2 * j]),     "l"(p0));
            asm("fma.rn.f32x2 %0, %1, %2, %0;" : "+l"(a1) : "l"(w2[2 * j + 1]), "l"(p1));
            asm("fma.rn.f32x2 %0, %1, %2, %0;" : "+l"(a2) : "l"(w2[2 * j + 2]), "l"(p2));
            asm("fma.rn.f32x2 %0, %1, %2, %0;" : "+l"(a3) : "l"(w2[2 * j + 3]), "l"(p3));
        }
        if (step > 0) { if (p) ph1 ^= 1; else ph0 ^= 1; }

        float l0, h0f, l1, h1f, l2, h2f, l3, h3f;
        asm("mov.b64 {%0,%1}, %2;" : "=f"(l0), "=f"(h0f) : "l"(a0));
        asm("mov.b64 {%0,%1}, %2;" : "=f"(l1), "=f"(h1f) : "l"(a1));
        asm("mov.b64 {%0,%1}, %2;" : "=f"(l2), "=f"(h2f) : "l"(a2));
        asm("mov.b64 {%0,%1}, %2;" : "=f"(l3), "=f"(h3f) : "l"(a3));
        red[p][tid] = ((l0 + h0f) + (l1 + h1f)) + ((l2 + h2f) + (l3 + h3f));
        __syncthreads();   // all-sources join (licenses buffer overwrite)

        if (tid < 32) {
            const float* r = red[p];
            float di = (r[tid]       + r[128 + tid]) + (r[256 + tid] + r[384 + tid]);
            float df = (r[32 + tid]  + r[160 + tid]) + (r[288 + tid] + r[416 + tid]);
            float dg = (r[64 + tid]  + r[192 + tid]) + (r[320 + tid] + r[448 + tid]);
            float dz = (r[96 + tid]  + r[224 + tid]) + (r[352 + tid] + r[480 + tid]);
            float ig = fast_sigmoid(pxi + di);
            float fg = fast_sigmoid(pxf + df);
            float gg = fast_tanh(pxg + dg);
            float og = fast_sigmoid(pxo + dz);
            c_reg = fg * c_reg + ig * gg;
            float hnew = og * fast_tanh(c_reg);

            if (step + 1 < SLEN) {
                int wb = p ^ 1;
#pragma unroll
                for (int rr = 0; rr < 8; rr++) {
                    uint32_t ra = wb ? rdst1[rr] : rdst0[rr];
                    asm volatile("st.shared::cluster.f32 [%0], %1;"
                                 :: "r"(ra), "f"(hnew) : "memory");
                }
                __syncwarp();   // stamp's release is cumulative over warp stores
                if (tid < 8) {
                    uint32_t rm = wb ? rmb1 : rmb0;
                    asm volatile("mbarrier.arrive.release.cluster.shared::cluster.b64 _, [%0];"
                                 :: "r"(rm) : "memory");
                }
            }
            hout[s * HDIM + u] = hnew;   // off the comm critical path
        }
        pxi = npxi; pxf = npxf; pxg = npxg; pxo = npxo;
    }
    asm volatile("barrier.cluster.arrive.aligned;" ::: "memory");
    asm volatile("barrier.cluster.wait.aligned;" ::: "memory");
    if (tid == 0) {
#pragma unroll
        for (int s = 0; s < 16; s++)
            asm volatile("mbarrier.inval.shared.b64 [%0];"
                         :: "r"(mbar_sa + s * 8) : "memory");
    }
}

// ---------------- K3: feats ----------------
#define FEATS_SMEM ((512 * 33 + 8 * 512) * 4)
__global__ __launch_bounds__(256) void feats_kernel(const float* __restrict__ w_tag,
                                                    const float* __restrict__ b_tag)
{
    extern __shared__ float fs[];
    float* wt = fs;
    float* hs = fs + 512 * 33;

    int tid = threadIdx.x;
    for (int idx = tid; idx < NTAG * 512; idx += 256) {
        int t = idx >> 9;
        int k = idx & 511;
        wt[k * 33 + t] = w_tag[idx];
    }
    __syncthreads();

    int warp = tid >> 5, lane = tid & 31;
    float bias = b_tag[lane];
    float* hrow = hs + warp * 512;

#pragma unroll
    for (int p = 0; p < 4; p++) {
        int s = blockIdx.x * 32 + p * 8 + warp;
        float4* dsth = (float4*)hrow;
        const float4* hf4 = (const float4*)(g_h[0] + s * HDIM);
        const float4* hb4 = (const float4*)(g_h[1] + s * HDIM);
        dsth[lane] = hf4[lane];
        dsth[32 + lane] = hf4[32 + lane];
        dsth[64 + lane] = hb4[lane];
        dsth[96 + lane] = hb4[32 + lane];
        __syncwarp();
        float a0 = 0.f, a1 = 0.f, a2 = 0.f, a3 = 0.f;
#pragma unroll 8
        for (int k = 0; k < 512; k += 4) {
            float4 h = *(const float4*)(hrow + k);
            a0 += wt[(k + 0) * 33 + lane] * h.x;
            a1 += wt[(k + 1) * 33 + lane] * h.y;
            a2 += wt[(k + 2) * 33 + lane] * h.z;
            a3 += wt[(k + 3) * 33 + lane] * h.w;
        }
        g_feats[s * NTAG + lane] = (a0 + a1) + (a2 + a3) + bias;
        __syncwarp();
    }
}

// ---------------- K4: Viterbi ----------------
__global__ void __launch_bounds__(32) viterbi_kernel(const float* __restrict__ trans,
                                                     float* __restrict__ out,
                                                     int out_size)
{
    extern __shared__ unsigned char bp[];
    int n = threadIdx.x;
    float tr[NTAG];
#pragma unroll
    for (int p = 0; p < NTAG; p++) tr[p] = trans[n * NTAG + p];

    float fv = (n == START_TAG) ? 0.f : NEGV;
    float f0 = g_feats[n];
    float f1 = g_feats[NTAG + n];
    for (int t = 0; t < SLEN; t++) {
        float f2 = (t + 2 < SLEN) ? g_feats[(t + 2) * NTAG + n] : 0.f;
        float v[NTAG];
#pragma unroll
        for (int p = 0; p < NTAG; p++)
            v[p] = __shfl_sync(0xffffffffu, fv, p) + tr[p];
        float bv[16]; int bi[16];
#pragma unroll
        for (int q2 = 0; q2 < 16; q2++) {
            bool take = v[q2 + 16] > v[q2];
            bv[q2] = take ? v[q2 + 16] : v[q2];
            bi[q2] = take ? q2 + 16 : q2;
        }
#pragma unroll
        for (int st = 8; st > 0; st >>= 1) {
#pragma unroll
            for (int q2 = 0; q2 < 16; q2++) {
                if (q2 < st) {
                    bool take = (bv[q2 + st] > bv[q2]) ||
                                (bv[q2 + st] == bv[q2] && bi[q2 + st] < bi[q2]);
                    bv[q2] = take ? bv[q2 + st] : bv[q2];
                    bi[q2] = take ? bi[q2 + st] : bi[q2];
                }
            }
        }
        fv = bv[0] + f0;
        bp[t * NTAG + n] = (unsigned char)bi[0];
        f0 = f1; f1 = f2;
    }
    float term = fv + trans[STOP_TAG * NTAG + n];
    float bvv = term;
    int bii = n;
#pragma unroll
    for (int off = 16; off > 0; off >>= 1) {
        float ov = __shfl_down_sync(0xffffffffu, bvv, off);
        int oi = __shfl_down_sync(0xffffffffu, bii, off);
        if (ov > bvv || (ov == bvv && oi < bii)) { bvv = ov; bii = oi; }
    }
    if (n == 0) {
        if (out_size > 0) out[0] = bvv;
        int tag = bii;
        if (out_size > SLEN) out[SLEN] = (float)tag;
        for (int t = SLEN - 2; t >= 0; t--) {
            tag = bp[(t + 1) * NTAG + tag];
            if (1 + t < out_size) out[1 + t] = (float)tag;
        }
    }
}

// ---------------- launch -----------------------------------------------------
extern "C" void kernel_launch(void* const* d_in, const int* in_sizes, int n_in,
                              void* d_out, int out_size)
{
    const int*   sent   = (const int*)d_in[0];
    const float* embed  = (const float*)d_in[1];
    const float* w_ih_f = (const float*)d_in[2];
    const float* w_hh_f = (const float*)d_in[3];
    const float* b_f    = (const float*)d_in[4];
    const float* w_ih_b = (const float*)d_in[5];
    const float* w_hh_b = (const float*)d_in[6];
    const float* b_b    = (const float*)d_in[7];
    const float* w_tag  = (const float*)d_in[8];
    const float* b_tag  = (const float*)d_in[9];
    const float* trans  = (const float*)d_in[10];
    const float* h0     = (const float*)d_in[11];
    const float* c0     = (const float*)d_in[12];
    float* out = (float*)d_out;

    cudaFuncSetAttribute(feats_kernel,
                         cudaFuncAttributeMaxDynamicSharedMemorySize, FEATS_SMEM);
    cudaFuncSetAttribute(viterbi_kernel,
                         cudaFuncAttributeMaxDynamicSharedMemorySize, SLEN * NTAG);

    dim3 gg(SLEN / BM, (4 * HDIM) / BN, 2);
    px_gemm_kernel<<<gg, 256>>>(sent, embed, w_ih_f, b_f, w_ih_b, b_b);

    lstm_kernel<<<16, 512>>>(w_hh_f, w_hh_b, h0, c0);

    feats_kernel<<<SLEN / 32, 256, FEATS_SMEM>>>(w_tag, b_tag);

    viterbi_kernel<<<1, 32, SLEN * NTAG>>>(trans, out, out_size);
}